// round 1
// baseline (speedup 1.0000x reference)
#include <cuda_runtime.h>

// PS-ROI Align:
//   img : (1, 20, 20, 49*32) fp32   (pixel-major, channel c = bin*32 + alpha)
//   rois: (1, 8192, 4) fp32         (x, y, w, h)
//   out : (1, 8192, 7, 7, 32) fp32  (flat: roi*1568 + bin*32 + alpha, bin = bx*7+by)
//
// Per (roi,bin): average of a 2x2 sample grid of bilinear interps. The sample
// grid is a tensor product, so the summed bilinear weights factorize into a
// 3x3 outer product WY[dy]*WX[dx] (sample spacing < 1 pixel guarantees a
// 3-wide footprint per axis). Validity masking factorizes too.
//
// Mapping: block = (bin, chunk of 1024 rois). The bin's feature slice
// (20*20*32 fp32 = 51.2KB) is staged to SMEM; each 8-lane thread group
// handles one (roi,bin) with one float4 (4 alphas) per lane -> all LDS.128
// are 128B-aligned conflict-free, all STG.128 coalesced per group.

namespace {
constexpr int POOLN       = 7;
constexpr int TOTAL_BINS  = 49;
constexpr int ALPHA       = 32;
constexpr int HH          = 20;
constexpr int WW          = 20;
constexpr int THREADS     = 256;
constexpr int GROUPS      = THREADS / 8;   // 32 (roi,bin) groups per block
constexpr int ROIS_PER_BLOCK = 1024;
constexpr int SMEM_F4     = HH * WW * (ALPHA / 4);  // 3200 float4
constexpr int SMEM_BYTES  = SMEM_F4 * 16;           // 51200 B
}

// Build base row index + 3 factorized weights for one axis from the two
// sample coordinates (c2 >= c1, c2-c1 < 1).
__device__ __forceinline__ void axis_weights(float c1, float c2,
                                             int& base,
                                             float& W0, float& W1, float& W2)
{
    float f1 = floorf(c1), f2 = floorf(c2);
    float w1 = c1 - f1,    w2 = c2 - f2;
    float v1 = (c1 >= 0.0f && c1 <= 19.0f) ? 1.0f : 0.0f;
    float v2 = (c2 >= 0.0f && c2 <= 19.0f) ? 1.0f : 0.0f;

    int a1 = min(max((int)f1, 0), 19);
    int b1 = min(a1 + 1, 19);
    int a2 = min(max((int)f2, 0), 19);
    int b2 = min(a2 + 1, 19);

    base = a1;
    int o1 = b1 - a1;                       // 0 or 1
    int o2 = min(max(a2 - a1, 0), 2);
    int o3 = min(max(b2 - a1, 0), 2);

    float u1 = v1 - v1 * w1;   // v1*(1-w1)
    float u2 = v1 * w1;
    float u3 = v2 - v2 * w2;   // v2*(1-w2)
    float u4 = v2 * w2;

    W0 = u1 + (o1 == 0 ? u2 : 0.0f) + (o2 == 0 ? u3 : 0.0f) + (o3 == 0 ? u4 : 0.0f);
    W1 =      (o1 == 1 ? u2 : 0.0f) + (o2 == 1 ? u3 : 0.0f) + (o3 == 1 ? u4 : 0.0f);
    W2 =                              (o2 == 2 ? u3 : 0.0f) + (o3 == 2 ? u4 : 0.0f);
}

__global__ __launch_bounds__(THREADS, 2)
void psroi_align_kernel(const float4* __restrict__ img4,
                        const float4* __restrict__ rois4,
                        float4* __restrict__ out4)
{
    extern __shared__ float4 s4[];   // [pix=y*20+x][aq=0..7] float4

    const int bin = blockIdx.x;      // 0..48
    const int bx  = bin / POOLN;     // x bin index (reference: bin_x = b//7)
    const int by  = bin % POOLN;     // y bin index

    // ---- stage this bin's feature slice into SMEM ----
    {
        const int binoff4 = bin * (ALPHA / 4);      // +bin*8 float4 within pixel
        #pragma unroll 4
        for (int p = threadIdx.x; p < SMEM_F4; p += THREADS) {
            int pix = p >> 3;
            int aq  = p & 7;
            s4[p] = img4[pix * (TOTAL_BINS * ALPHA / 4) + binoff4 + aq];
        }
    }
    __syncthreads();

    const int grp = threadIdx.x >> 3;   // 0..31 : which (roi) in this iter
    const int q   = threadIdx.x & 7;    // alpha quad 0..7
    const int roi_base = blockIdx.y * ROIS_PER_BLOCK;

    #pragma unroll 1
    for (int it = 0; it < ROIS_PER_BLOCK / GROUPS; ++it) {
        const int roi = roi_base + it * GROUPS + grp;
        const float4 r = __ldg(&rois4[roi]);   // x, y, w, h (broadcast across 8 lanes)

        const float stepx = r.z * (1.0f / 7.0f);
        const float stepy = r.w * (1.0f / 7.0f);
        const float sc = 19.0f / 20.0f;

        const float cx1 = (r.x + (float)bx * stepx) * sc;
        const float cx2 = (r.x + (float)(bx + 1) * stepx) * sc;
        const float cy1 = (r.y + (float)by * stepy) * sc;
        const float cy2 = (r.y + (float)(by + 1) * stepy) * sc;

        int by0, bx0;
        float WY0, WY1, WY2, WX0, WX1, WX2;
        axis_weights(cy1, cy2, by0, WY0, WY1, WY2);
        axis_weights(cx1, cx2, bx0, WX0, WX1, WX2);

        // clamped footprint indices (zero-weight cells may be clamped; safe)
        const int x0 = bx0;
        const int x1 = min(bx0 + 1, 19);
        const int x2 = min(bx0 + 2, 19);
        const int r0 = by0 * WW;
        const int r1 = min(by0 + 1, 19) * WW;
        const int r2 = min(by0 + 2, 19) * WW;

        float4 acc = make_float4(0.0f, 0.0f, 0.0f, 0.0f);

        #define SAMP(ROW, COL, WGT) do {                      \
            float4 v_ = s4[((ROW) + (COL)) * 8 + q];          \
            acc.x = fmaf((WGT), v_.x, acc.x);                 \
            acc.y = fmaf((WGT), v_.y, acc.y);                 \
            acc.z = fmaf((WGT), v_.z, acc.z);                 \
            acc.w = fmaf((WGT), v_.w, acc.w);                 \
        } while (0)

        // always-hot 2x2 core
        SAMP(r0, x0, WY0 * WX0);
        SAMP(r0, x1, WY0 * WX1);
        SAMP(r1, x0, WY1 * WX0);
        SAMP(r1, x1, WY1 * WX1);
        // 3rd column / 3rd row are zero ~40% of the time each -> skip to
        // save SMEM wavefronts (divergence prunes inactive groups' 128B chunks)
        if (WX2 != 0.0f) {
            SAMP(r0, x2, WY0 * WX2);
            SAMP(r1, x2, WY1 * WX2);
        }
        if (WY2 != 0.0f) {
            SAMP(r2, x0, WY2 * WX0);
            SAMP(r2, x1, WY2 * WX1);
            if (WX2 != 0.0f) SAMP(r2, x2, WY2 * WX2);
        }
        #undef SAMP

        acc.x *= 0.25f; acc.y *= 0.25f; acc.z *= 0.25f; acc.w *= 0.25f;

        // out flat float4 index: (roi*1568 + bin*32)/4 + q
        out4[roi * (TOTAL_BINS * ALPHA / 4) + bin * (ALPHA / 4) + q] = acc;
    }
}

extern "C" void kernel_launch(void* const* d_in, const int* in_sizes, int n_in,
                              void* d_out, int out_size)
{
    const float* p0 = (const float*)d_in[0];
    const float* p1 = (const float*)d_in[1];
    const float* img  = p0;
    const float* rois = p1;
    int rois_elems = in_sizes[1];
    if (in_sizes[0] < in_sizes[1]) {   // inputs arrived swapped
        img = p1; rois = p0; rois_elems = in_sizes[0];
    }
    const int R = rois_elems / 4;      // 8192

    cudaFuncSetAttribute(psroi_align_kernel,
                         cudaFuncAttributeMaxDynamicSharedMemorySize, SMEM_BYTES);

    dim3 grid(TOTAL_BINS, R / ROIS_PER_BLOCK);   // 49 x 8
    psroi_align_kernel<<<grid, THREADS, SMEM_BYTES>>>(
        (const float4*)img, (const float4*)rois, (float4*)d_out);
}

// round 2
// speedup vs baseline: 1.0651x; 1.0651x over previous
#include <cuda_runtime.h>

// PS-ROI Align, two-phase:
//   Phase 1 (tiny): per (roi, axis-position) compute factorized 3-tap bilinear
//     weights + clamped indices -> tables g_TX / g_TY (float4 each).
//   Phase 2: block = (bin, 512-roi chunk). Bin's feature slice (20*20*32 fp32 =
//     51.2KB) staged in SMEM; 8-lane groups each produce one (roi,bin) float4x8
//     output row from <=9 conflict-free LDS.128 + FMAs.
//
// Weight factorization: the 2x2 sample grid per bin is a tensor product with
// sample spacing < 1px, so summed bilinear weights collapse to a 3x3 outer
// product WY[0..2] x WX[0..2]; validity masking factorizes identically.

namespace {
constexpr int POOLN       = 7;
constexpr int TOTAL_BINS  = 49;
constexpr int ALPHA       = 32;
constexpr int HH          = 20;
constexpr int WW          = 20;
constexpr int THREADS     = 256;
constexpr int GROUPS      = THREADS / 8;        // 32 rois in flight per iter
constexpr int ROIS_PER_BLOCK = 512;
constexpr int MAX_ROIS    = 8192;
constexpr int SMEM_F4     = HH * WW * (ALPHA / 4);  // 3200 float4
constexpr int SMEM_BYTES  = SMEM_F4 * 16;           // 51200 B
}

// Per-(roi, axis position) weight record:
//   .x = bitcast int: i0 | i1<<8 | i2<<16  (clamped footprint indices)
//   .y/.z/.w = W0, W1, W2 (factorized weights incl. validity mask)
__device__ float4 g_TX[MAX_ROIS * POOLN];
__device__ float4 g_TY[MAX_ROIS * POOLN];

__device__ __forceinline__ float4 axis_record(float origin, float step, int pos)
{
    const float sc = 19.0f / 20.0f;
    float c1 = (origin + (float)pos * step) * sc;
    float c2 = (origin + (float)(pos + 1) * step) * sc;

    float f1 = floorf(c1), f2 = floorf(c2);
    float w1 = c1 - f1,    w2 = c2 - f2;
    float v1 = (c1 >= 0.0f && c1 <= 19.0f) ? 1.0f : 0.0f;
    float v2 = (c2 >= 0.0f && c2 <= 19.0f) ? 1.0f : 0.0f;

    int a1 = min(max((int)f1, 0), 19);
    int b1 = min(a1 + 1, 19);
    int a2 = min(max((int)f2, 0), 19);
    int b2 = min(a2 + 1, 19);

    int o1 = b1 - a1;                     // 0 or 1
    int o2 = min(max(a2 - a1, 0), 2);
    int o3 = min(max(b2 - a1, 0), 2);

    float u1 = v1 - v1 * w1;
    float u2 = v1 * w1;
    float u3 = v2 - v2 * w2;
    float u4 = v2 * w2;

    float W0 = u1 + (o1 == 0 ? u2 : 0.0f) + (o2 == 0 ? u3 : 0.0f) + (o3 == 0 ? u4 : 0.0f);
    float W1 =      (o1 == 1 ? u2 : 0.0f) + (o2 == 1 ? u3 : 0.0f) + (o3 == 1 ? u4 : 0.0f);
    float W2 =                              (o2 == 2 ? u3 : 0.0f) + (o3 == 2 ? u4 : 0.0f);

    int i0 = a1;
    int i1 = min(a1 + 1, 19);
    int i2 = min(a1 + 2, 19);
    int pack = i0 | (i1 << 8) | (i2 << 16);

    float4 rec;
    rec.x = __int_as_float(pack);
    rec.y = W0; rec.z = W1; rec.w = W2;
    return rec;
}

__global__ void psroi_setup_kernel(const float4* __restrict__ rois4, int R)
{
    int idx = blockIdx.x * blockDim.x + threadIdx.x;   // roi*7 + pos
    if (idx >= R * POOLN) return;
    int roi = idx / POOLN;
    int pos = idx - roi * POOLN;
    float4 r = __ldg(&rois4[roi]);                     // x, y, w, h
    g_TX[idx] = axis_record(r.x, r.z * (1.0f / 7.0f), pos);
    g_TY[idx] = axis_record(r.y, r.w * (1.0f / 7.0f), pos);
}

__global__ __launch_bounds__(THREADS, 4)
void psroi_main_kernel(const float4* __restrict__ img4,
                       float4* __restrict__ out4)
{
    extern __shared__ float4 s4[];     // [pix = y*20+x][aq 0..7]

    const int bin = blockIdx.x;        // 0..48
    const int bx  = bin / POOLN;
    const int by  = bin % POOLN;

    // stage this bin's slice (51.2KB) into SMEM
    {
        const int binoff4 = bin * (ALPHA / 4);
        #pragma unroll 4
        for (int p = threadIdx.x; p < SMEM_F4; p += THREADS) {
            int pix = p >> 3;
            int aq  = p & 7;
            s4[p] = img4[pix * (TOTAL_BINS * ALPHA / 4) + binoff4 + aq];
        }
    }
    __syncthreads();

    const int grp = threadIdx.x >> 3;
    const int q   = threadIdx.x & 7;
    const int roi_base = blockIdx.y * ROIS_PER_BLOCK;

    int txi = (roi_base + grp) * POOLN + bx;
    int tyi = (roi_base + grp) * POOLN + by;

    #pragma unroll 2
    for (int it = 0; it < ROIS_PER_BLOCK / GROUPS; ++it) {
        const int roi = roi_base + it * GROUPS + grp;
        const float4 wx = __ldg(&g_TX[txi]);
        const float4 wy = __ldg(&g_TY[tyi]);
        txi += GROUPS * POOLN;
        tyi += GROUPS * POOLN;

        const int px = __float_as_int(wx.x);
        const int py = __float_as_int(wy.x);
        const int x0 = px & 255, x1 = (px >> 8) & 255, x2 = (px >> 16) & 255;
        const int r0 = (py & 255) * WW;
        const int r1 = ((py >> 8) & 255) * WW;
        const int r2 = ((py >> 16) & 255) * WW;

        float4 acc = make_float4(0.0f, 0.0f, 0.0f, 0.0f);

        #define SAMP(ROW, COL, WGT) do {                  \
            float4 v_ = s4[((ROW) + (COL)) * 8 + q];      \
            acc.x = fmaf((WGT), v_.x, acc.x);             \
            acc.y = fmaf((WGT), v_.y, acc.y);             \
            acc.z = fmaf((WGT), v_.z, acc.z);             \
            acc.w = fmaf((WGT), v_.w, acc.w);             \
        } while (0)

        SAMP(r0, x0, wy.y * wx.y);
        SAMP(r0, x1, wy.y * wx.z);
        SAMP(r1, x0, wy.z * wx.y);
        SAMP(r1, x1, wy.z * wx.z);
        if (wx.w != 0.0f) {
            SAMP(r0, x2, wy.y * wx.w);
            SAMP(r1, x2, wy.z * wx.w);
        }
        if (wy.w != 0.0f) {
            SAMP(r2, x0, wy.w * wx.y);
            SAMP(r2, x1, wy.w * wx.z);
            if (wx.w != 0.0f) SAMP(r2, x2, wy.w * wx.w);
        }
        #undef SAMP

        acc.x *= 0.25f; acc.y *= 0.25f; acc.z *= 0.25f; acc.w *= 0.25f;

        out4[roi * (TOTAL_BINS * ALPHA / 4) + bin * (ALPHA / 4) + q] = acc;
    }
}

extern "C" void kernel_launch(void* const* d_in, const int* in_sizes, int n_in,
                              void* d_out, int out_size)
{
    const float* p0 = (const float*)d_in[0];
    const float* p1 = (const float*)d_in[1];
    const float* img  = p0;
    const float* rois = p1;
    int rois_elems = in_sizes[1];
    if (in_sizes[0] < in_sizes[1]) {
        img = p1; rois = p0; rois_elems = in_sizes[0];
    }
    const int R = rois_elems / 4;      // 8192

    {
        int total = R * POOLN;
        int blocks = (total + 255) / 256;
        psroi_setup_kernel<<<blocks, 256>>>((const float4*)rois, R);
    }

    cudaFuncSetAttribute(psroi_main_kernel,
                         cudaFuncAttributeMaxDynamicSharedMemorySize, SMEM_BYTES);
    dim3 grid(TOTAL_BINS, R / ROIS_PER_BLOCK);     // 49 x 16 = 784 blocks
    psroi_main_kernel<<<grid, THREADS, SMEM_BYTES>>>(
        (const float4*)img, (float4*)d_out);
}

// round 3
// speedup vs baseline: 1.0727x; 1.0072x over previous
#include <cuda_runtime.h>
#include <cstdint>

// PS-ROI Align, two-phase, branchless f32x2 inner loop.
//   Phase 1: per (roi, axis-pos) factorized 3-tap weights + clamped indices.
//   Phase 2: block = (bin, 256-roi chunk); bin slice (51.2KB) in SMEM; each
//   8-lane group produces one (roi,bin): 9 x (LDS.128 as v2.b64 + mul.f32x2 +
//   2 fma.f32x2), no branches (zero-weight cells are arithmetic no-ops).

namespace {
constexpr int POOLN       = 7;
constexpr int TOTAL_BINS  = 49;
constexpr int ALPHA       = 32;
constexpr int HH          = 20;
constexpr int WW          = 20;
constexpr int THREADS     = 256;
constexpr int GROUPS      = THREADS / 8;        // 32 rois per iter
constexpr int ROIS_PER_BLOCK = 256;
constexpr int MAX_ROIS    = 8192;
constexpr int SMEM_F4     = HH * WW * (ALPHA / 4);  // 3200 float4
constexpr int SMEM_BYTES  = SMEM_F4 * 16;           // 51200 B
}

// .x = bitcast int: i0 | i1<<8 | i2<<16 (clamped indices); .y/.z/.w = W0,W1,W2
__device__ float4 g_TX[MAX_ROIS * POOLN];
__device__ float4 g_TY[MAX_ROIS * POOLN];

__device__ __forceinline__ float4 axis_record(float origin, float step, int pos)
{
    const float sc = 19.0f / 20.0f;
    float c1 = (origin + (float)pos * step) * sc;
    float c2 = (origin + (float)(pos + 1) * step) * sc;

    float f1 = floorf(c1), f2 = floorf(c2);
    float w1 = c1 - f1,    w2 = c2 - f2;
    float v1 = (c1 >= 0.0f && c1 <= 19.0f) ? 1.0f : 0.0f;
    float v2 = (c2 >= 0.0f && c2 <= 19.0f) ? 1.0f : 0.0f;

    int a1 = min(max((int)f1, 0), 19);
    int b1 = min(a1 + 1, 19);
    int a2 = min(max((int)f2, 0), 19);
    int b2 = min(a2 + 1, 19);

    int o1 = b1 - a1;
    int o2 = min(max(a2 - a1, 0), 2);
    int o3 = min(max(b2 - a1, 0), 2);

    float u1 = v1 - v1 * w1;
    float u2 = v1 * w1;
    float u3 = v2 - v2 * w2;
    float u4 = v2 * w2;

    float W0 = u1 + (o1 == 0 ? u2 : 0.0f) + (o2 == 0 ? u3 : 0.0f) + (o3 == 0 ? u4 : 0.0f);
    float W1 =      (o1 == 1 ? u2 : 0.0f) + (o2 == 1 ? u3 : 0.0f) + (o3 == 1 ? u4 : 0.0f);
    float W2 =                              (o2 == 2 ? u3 : 0.0f) + (o3 == 2 ? u4 : 0.0f);

    int i0 = a1;
    int i1 = min(a1 + 1, 19);
    int i2 = min(a1 + 2, 19);

    float4 rec;
    rec.x = __int_as_float(i0 | (i1 << 8) | (i2 << 16));
    rec.y = W0; rec.z = W1; rec.w = W2;
    return rec;
}

__global__ void psroi_setup_kernel(const float4* __restrict__ rois4, int R)
{
    int idx = blockIdx.x * blockDim.x + threadIdx.x;   // roi*7 + pos
    if (idx >= R * POOLN) return;
    int roi = idx / POOLN;
    int pos = idx - roi * POOLN;
    float4 r = __ldg(&rois4[roi]);
    g_TX[idx] = axis_record(r.x, r.z * (1.0f / 7.0f), pos);
    g_TY[idx] = axis_record(r.y, r.w * (1.0f / 7.0f), pos);
}

// ---- packed f32x2 helpers ----
__device__ __forceinline__ unsigned long long pack2(float a) {
    unsigned long long r;
    asm("mov.b64 %0, {%1, %1};" : "=l"(r) : "f"(a));
    return r;
}
__device__ __forceinline__ unsigned long long mul2(unsigned long long a,
                                                   unsigned long long b) {
    unsigned long long r;
    asm("mul.rn.f32x2 %0, %1, %2;" : "=l"(r) : "l"(a), "l"(b));
    return r;
}
__device__ __forceinline__ void fma2(unsigned long long& d,
                                     unsigned long long a,
                                     unsigned long long b) {
    asm("fma.rn.f32x2 %0, %1, %2, %0;" : "+l"(d) : "l"(a), "l"(b));
}
__device__ __forceinline__ void lds128(unsigned long long& v0,
                                       unsigned long long& v1,
                                       uint32_t addr) {
    asm("ld.shared.v2.b64 {%0, %1}, [%2];" : "=l"(v0), "=l"(v1) : "r"(addr));
}

__global__ __launch_bounds__(THREADS, 4)
void psroi_main_kernel(const float4* __restrict__ img4,
                       ulonglong2* __restrict__ out2)
{
    extern __shared__ float4 s4[];     // [pix = y*20+x][aq 0..7]

    const int bin = blockIdx.x;        // 0..48
    const int bx  = bin / POOLN;
    const int by  = bin % POOLN;

    {   // stage this bin's slice (51.2KB) into SMEM
        const int binoff4 = bin * (ALPHA / 4);
        #pragma unroll 4
        for (int p = threadIdx.x; p < SMEM_F4; p += THREADS) {
            int pix = p >> 3;
            int aq  = p & 7;
            s4[p] = img4[pix * (TOTAL_BINS * ALPHA / 4) + binoff4 + aq];
        }
    }
    __syncthreads();

    const int grp = threadIdx.x >> 3;
    const int q   = threadIdx.x & 7;
    const int roi_base = blockIdx.y * ROIS_PER_BLOCK;

    const uint32_t sbase =
        (uint32_t)__cvta_generic_to_shared(s4) + (uint32_t)(q * 16);
    const unsigned long long quarter2 = pack2(0.25f);

    int txi = (roi_base + grp) * POOLN + bx;
    int tyi = (roi_base + grp) * POOLN + by;

    #pragma unroll 2
    for (int it = 0; it < ROIS_PER_BLOCK / GROUPS; ++it) {
        const int roi = roi_base + it * GROUPS + grp;
        const float4 wx = __ldg(&g_TX[txi]);
        const float4 wy = __ldg(&g_TY[tyi]);
        txi += GROUPS * POOLN;
        tyi += GROUPS * POOLN;

        const uint32_t px = (uint32_t)__float_as_int(wx.x);
        const uint32_t py = (uint32_t)__float_as_int(wy.x);
        // column byte offsets: x*32*4B = x<<7 ; row byte offsets: y*20*128
        const uint32_t c0 = sbase + ((px & 255u) << 7);
        const uint32_t c1 = sbase + (((px >> 8) & 255u) << 7);
        const uint32_t c2 = sbase + (((px >> 16) & 255u) << 7);
        const uint32_t r0 = (py & 255u) * 2560u;
        const uint32_t r1 = ((py >> 8) & 255u) * 2560u;
        const uint32_t r2 = ((py >> 16) & 255u) * 2560u;

        const unsigned long long wx0 = pack2(wx.y);
        const unsigned long long wx1 = pack2(wx.z);
        const unsigned long long wx2 = pack2(wx.w);
        const unsigned long long wy0 = pack2(wy.y);
        const unsigned long long wy1 = pack2(wy.z);
        const unsigned long long wy2 = pack2(wy.w);

        unsigned long long a01 = 0ull, a23 = 0ull;

        #define SAMP(RW, CW, ADDR) do {                 \
            unsigned long long v0_, v1_;                \
            lds128(v0_, v1_, (ADDR));                   \
            unsigned long long w_ = mul2((RW), (CW));   \
            fma2(a01, w_, v0_);                         \
            fma2(a23, w_, v1_);                         \
        } while (0)

        SAMP(wy0, wx0, r0 + c0);
        SAMP(wy0, wx1, r0 + c1);
        SAMP(wy0, wx2, r0 + c2);
        SAMP(wy1, wx0, r1 + c0);
        SAMP(wy1, wx1, r1 + c1);
        SAMP(wy1, wx2, r1 + c2);
        SAMP(wy2, wx0, r2 + c0);
        SAMP(wy2, wx1, r2 + c1);
        SAMP(wy2, wx2, r2 + c2);
        #undef SAMP

        a01 = mul2(a01, quarter2);
        a23 = mul2(a23, quarter2);

        ulonglong2 o; o.x = a01; o.y = a23;
        out2[roi * (TOTAL_BINS * ALPHA / 4) + bin * (ALPHA / 4) + q] = o;
    }
}

extern "C" void kernel_launch(void* const* d_in, const int* in_sizes, int n_in,
                              void* d_out, int out_size)
{
    const float* p0 = (const float*)d_in[0];
    const float* p1 = (const float*)d_in[1];
    const float* img  = p0;
    const float* rois = p1;
    int rois_elems = in_sizes[1];
    if (in_sizes[0] < in_sizes[1]) {
        img = p1; rois = p0; rois_elems = in_sizes[0];
    }
    const int R = rois_elems / 4;      // 8192

    {
        int total = R * POOLN;
        int blocks = (total + 255) / 256;
        psroi_setup_kernel<<<blocks, 256>>>((const float4*)rois, R);
    }

    cudaFuncSetAttribute(psroi_main_kernel,
                         cudaFuncAttributeMaxDynamicSharedMemorySize, SMEM_BYTES);
    dim3 grid(TOTAL_BINS, R / ROIS_PER_BLOCK);     // 49 x 32 = 1568 blocks
    psroi_main_kernel<<<grid, THREADS, SMEM_BYTES>>>(
        (const float4*)img, (ulonglong2*)d_out);
}